// round 8
// baseline (speedup 1.0000x reference)
#include <cuda_runtime.h>

// Fixed problem shape
#define BB   4
#define CC   256
#define HH   128
#define WW   256
#define NGRP 4
#define CG   64      // channels per group
#define WIN  9       // 1x9 window
#define CK   32      // channel chunk held in smem
#define SRS  264     // padded smem row: pixel w at col w+4, replicate pad 4 each side

__global__ __launch_bounds__(256, 3)
void crestereo_v64_kernel(const float* __restrict__ left,
                          const float* __restrict__ right,
                          const float* __restrict__ flow,
                          float* __restrict__ out)
{
    __shared__ float srw[CK][SRS];

    const int bh = blockIdx.x;
    const int b  = bh >> 7;          // bh / HH
    const int h  = bh & (HH - 1);
    const int w  = threadIdx.x;
    const int HW = HH * WW;

    // ---- per-pixel bilinear setup (invariant across channels) ----
    const float fx = flow[(((size_t)b * 2 + 0) * HH + h) * WW + w];
    const float fy = flow[(((size_t)b * 2 + 1) * HH + h) * WW + w];
    const float x = (float)w + fx;
    const float y = (float)h + fy;
    const float x0f = floorf(x);
    const float y0f = floorf(y);
    const int ix0 = (int)x0f;
    const int iy0 = (int)y0f;
    const float ax = x - x0f;
    const float ay = y - y0f;

    float w00 = (1.f - ax) * (1.f - ay);   // (x0, y0)
    float w01 = ax * (1.f - ay);           // (x1, y0)
    float w10 = (1.f - ax) * ay;           // (x0, y1)
    float w11 = ax * ay;                   // (x1, y1)

    const bool vx0 = (ix0     >= 0) & (ix0     <= WW - 1);
    const bool vx1 = (ix0 + 1 >= 0) & (ix0 + 1 <= WW - 1);
    const bool vy0 = (iy0     >= 0) & (iy0     <= HH - 1);
    const bool vy1 = (iy0 + 1 >= 0) & (iy0 + 1 <= HH - 1);
    if (!(vx0 & vy0)) w00 = 0.f;
    if (!(vx1 & vy0)) w01 = 0.f;
    if (!(vx0 & vy1)) w10 = 0.f;
    if (!(vx1 & vy1)) w11 = 0.f;

    // clamped coordinates
    const int x0c = min(max(ix0, 0), WW - 1);
    const int x1c = min(max(ix0 + 1, 0), WW - 1);
    const int y0c = min(max(iy0, 0), HH - 1);
    const int y1c = min(max(iy0 + 1, 0), HH - 1);

    // float2 gather: load pair at xlo = clamp(ix0, 0, W-2); fold weights onto
    // d.x (col xlo) / d.y (col xlo+1) according to where x0c/x1c actually land.
    const int xlo = min(max(ix0, 0), WW - 2);
    const float wlt = (x0c == xlo     ? w00 : 0.f) + (x1c == xlo     ? w01 : 0.f);
    const float wrt = (x0c == xlo + 1 ? w00 : 0.f) + (x1c == xlo + 1 ? w01 : 0.f);
    const float wlb = (x0c == xlo     ? w10 : 0.f) + (x1c == xlo     ? w11 : 0.f);
    const float wrb = (x0c == xlo + 1 ? w10 : 0.f) + (x1c == xlo + 1 ? w11 : 0.f);

    const int o_top = y0c * WW + xlo;   // float2-aligned? not guaranteed — use unaligned-safe loads
    const int o_bot = y1c * WW + xlo;

    const float* lbase = left  + (size_t)b * CC * HW + (size_t)h * WW + w;
    const float* rbase = right + (size_t)b * CC * HW;

    float acc[WIN];

    for (int g = 0; g < NGRP; ++g) {
#pragma unroll
        for (int k = 0; k < WIN; ++k) acc[k] = 0.f;

        for (int ch0 = g * CG; ch0 < (g + 1) * CG; ch0 += CK) {
            __syncthreads();   // protect previous chunk's readers

            // ---- phase 1: burst-gather CK channels, 2x LDG.64 per channel ----
#pragma unroll
            for (int cc = 0; cc < CK; ++cc) {
                const float* rb = rbase + (size_t)(ch0 + cc) * HW;
                // xlo is arbitrary parity; float2 needs 8B alignment only if we
                // use vector types. Use __ldg-style two-element unaligned load
                // via reinterpret on 4B-aligned addresses: build float2 manually
                // when misaligned is not allowed. Addresses are 4B-aligned;
                // float2 requires 8B. So load via 64-bit only when aligned:
                // simplest portable: two 32-bit loads would defeat the purpose.
                // Instead: rows are 256 floats; xlo in [0,254]. Use __builtin
                // memcpy-free path: ld.global.v2 requires alignment, so fall
                // back to cheating with long long loads at 4B alignment is
                // illegal. Use two loads packed by the compiler? No — use
                // unaligned-capable 64-bit integer load via PTX is also
                // alignment-constrained. Resolution: gather pair with one
                // 64-bit load at (addr & ~7) covering 2 floats only when
                // aligned... Simpler correct approach below: conditional pair.
                float t0, t1, b0, b1;
                if ((xlo & 1) == 0) {
                    const float2 dt = *(const float2*)(rb + o_top);
                    const float2 db = *(const float2*)(rb + o_bot);
                    t0 = dt.x; t1 = dt.y; b0 = db.x; b1 = db.y;
                } else {
                    t0 = rb[o_top];  t1 = rb[o_top + 1];
                    b0 = rb[o_bot];  b1 = rb[o_bot + 1];
                }
                float v = t0 * wlt;
                v = fmaf(t1, wrt, v);
                v = fmaf(b0, wlb, v);
                v = fmaf(b1, wrb, v);
                srw[cc][4 + w] = v;
                if (w == 0) {
                    srw[cc][0] = v; srw[cc][1] = v; srw[cc][2] = v; srw[cc][3] = v;
                }
                if (w == WW - 1) {
                    srw[cc][WW + 4] = v; srw[cc][WW + 5] = v;
                    srw[cc][WW + 6] = v; srw[cc][WW + 7] = v;
                }
            }
            __syncthreads();

            // ---- phase 2: 9-tap sliding-window accumulate (taps at sp[0..8]) ----
#pragma unroll
            for (int cc = 0; cc < CK; ++cc) {
                const float lv = lbase[(size_t)(ch0 + cc) * HW];
                const float* sp = &srw[cc][w];
#pragma unroll
                for (int k = 0; k < WIN; ++k)
                    acc[k] = fmaf(lv, sp[k], acc[k]);
            }
        }

        // ---- write 9 output taps for this group (coalesced across w) ----
        const float scale = 1.f / (float)CG;
        float* ob = out + (((size_t)(b * NGRP + g) * WIN) * HH + h) * WW + w;
#pragma unroll
        for (int k = 0; k < WIN; ++k)
            ob[(size_t)k * HW] = acc[k] * scale;
    }
}

extern "C" void kernel_launch(void* const* d_in, const int* in_sizes, int n_in,
                              void* d_out, int out_size)
{
    const float* left  = (const float*)d_in[0];
    const float* right = (const float*)d_in[1];
    const float* flow  = (const float*)d_in[2];
    float* out = (float*)d_out;

    dim3 grid(BB * HH);   // 512 blocks: one per (b, h) row
    dim3 block(WW);       // 256 threads
    crestereo_v64_kernel<<<grid, block>>>(left, right, flow, out);
}

// round 9
// speedup vs baseline: 1.0200x; 1.0200x over previous
#include <cuda_runtime.h>

// Fixed problem shape
#define BB   4
#define CC   256
#define HH   128
#define WW   256
#define NGRP 4
#define CG   64      // channels per group
#define WIN  9       // 1x9 window
#define CK   32      // channel chunk held in smem
#define SRS  272     // padded smem row stride; 272 % 32 == 16 -> conflict-free LDS.64
                     // pixel w lives at col w+4 (replicate pad 4 each side)

__global__ __launch_bounds__(256, 3)
void crestereo_pair_kernel(const float* __restrict__ left,
                           const float* __restrict__ right,
                           const float* __restrict__ flow,
                           float* __restrict__ out)
{
    __shared__ float srw[CK][SRS];

    const int bh = blockIdx.x;
    const int b  = bh >> 7;          // bh / HH
    const int h  = bh & (HH - 1);
    const int w  = threadIdx.x;      // phase-1 pixel
    const int HW = HH * WW;

    // ---- per-pixel bilinear setup (identical math to R1) ----
    const float fx = flow[(((size_t)b * 2 + 0) * HH + h) * WW + w];
    const float fy = flow[(((size_t)b * 2 + 1) * HH + h) * WW + w];
    const float x = (float)w + fx;
    const float y = (float)h + fy;
    const float x0f = floorf(x);
    const float y0f = floorf(y);
    const int ix0 = (int)x0f;
    const int iy0 = (int)y0f;
    const float ax = x - x0f;
    const float ay = y - y0f;

    float w00 = (1.f - ax) * (1.f - ay);
    float w01 = ax * (1.f - ay);
    float w10 = (1.f - ax) * ay;
    float w11 = ax * ay;

    const bool vx0 = (ix0     >= 0) & (ix0     <= WW - 1);
    const bool vx1 = (ix0 + 1 >= 0) & (ix0 + 1 <= WW - 1);
    const bool vy0 = (iy0     >= 0) & (iy0     <= HH - 1);
    const bool vy1 = (iy0 + 1 >= 0) & (iy0 + 1 <= HH - 1);
    if (!(vx0 & vy0)) w00 = 0.f;
    if (!(vx1 & vy0)) w01 = 0.f;
    if (!(vx0 & vy1)) w10 = 0.f;
    if (!(vx1 & vy1)) w11 = 0.f;

    const int x0c = min(max(ix0, 0), WW - 1);
    const int x1c = min(max(ix0 + 1, 0), WW - 1);
    const int y0c = min(max(iy0, 0), HH - 1);
    const int y1c = min(max(iy0 + 1, 0), HH - 1);

    const int o00 = y0c * WW + x0c;
    const int o01 = y0c * WW + x1c;
    const int o10 = y1c * WW + x0c;
    const int o11 = y1c * WW + x1c;

    // phase-2 identity: pixel pair pg (pixels 2pg, 2pg+1), channel parity cs
    const int pg = w >> 1;
    const int cs = w & 1;

    const float* rbase = right + (size_t)b * CC * HW;
    // left pair base: left[.][h][2pg .. 2pg+1], 8B-aligned (even index)
    const float* lpair = left + (size_t)b * CC * HW + (size_t)h * WW + 2 * pg;

    float acc0[WIN], acc1[WIN];
    const float scale = 1.f / (float)CG;

    for (int g = 0; g < NGRP; ++g) {
#pragma unroll
        for (int k = 0; k < WIN; ++k) { acc0[k] = 0.f; acc1[k] = 0.f; }

        for (int ch0 = g * CG; ch0 < (g + 1) * CG; ch0 += CK) {
            __syncthreads();   // protect previous chunk's readers

            // ---- phase 1: burst-gather CK channels (EXACT R1 shape, map t->w) ----
#pragma unroll
            for (int cc = 0; cc < CK; ++cc) {
                const float* rb = rbase + (size_t)(ch0 + cc) * HW;
                float v = rb[o00] * w00;
                v = fmaf(rb[o01], w01, v);
                v = fmaf(rb[o10], w10, v);
                v = fmaf(rb[o11], w11, v);
                srw[cc][4 + w] = v;
                if (w == 0) {
                    srw[cc][0] = v; srw[cc][1] = v; srw[cc][2] = v; srw[cc][3] = v;
                }
                if (w == WW - 1) {
                    srw[cc][WW + 4] = v; srw[cc][WW + 5] = v;
                    srw[cc][WW + 6] = v; srw[cc][WW + 7] = v;
                }
            }
            __syncthreads();

            // ---- phase 2: pixel-pair consume (5x LDS.64 serve 18 taps) ----
#pragma unroll
            for (int i = 0; i < CK / 2; ++i) {
                const int cc = 2 * i + cs;
                const float2 lv = *(const float2*)(lpair + (size_t)(ch0 + cc) * HW);
                const float* sp = &srw[cc][2 * pg];   // window cols 2pg .. 2pg+9
                float tb[10];
#pragma unroll
                for (int j = 0; j < 5; ++j) {
                    const float2 d = *(const float2*)(sp + 2 * j);
                    tb[2 * j]     = d.x;
                    tb[2 * j + 1] = d.y;
                }
#pragma unroll
                for (int k = 0; k < WIN; ++k) {
                    acc0[k] = fmaf(lv.x, tb[k],     acc0[k]);
                    acc1[k] = fmaf(lv.y, tb[k + 1], acc1[k]);
                }
            }
        }

        // ---- merge channel-parity partials within each pixel pair ----
#pragma unroll
        for (int k = 0; k < WIN; ++k) {
            acc0[k] += __shfl_xor_sync(0xffffffffu, acc0[k], 1);
            acc1[k] += __shfl_xor_sync(0xffffffffu, acc1[k], 1);
        }

        // even thread writes pixel 2pg (acc0), odd writes 2pg+1 (acc1): col == t
        float* ob = out + (((size_t)(b * NGRP + g) * WIN) * HH + h) * WW + w;
#pragma unroll
        for (int k = 0; k < WIN; ++k)
            ob[(size_t)k * HW] = (cs ? acc1[k] : acc0[k]) * scale;
    }
}

extern "C" void kernel_launch(void* const* d_in, const int* in_sizes, int n_in,
                              void* d_out, int out_size)
{
    const float* left  = (const float*)d_in[0];
    const float* right = (const float*)d_in[1];
    const float* flow  = (const float*)d_in[2];
    float* out = (float*)d_out;

    dim3 grid(BB * HH);   // 512 blocks: one per (b, h) row
    dim3 block(WW);       // 256 threads
    crestereo_pair_kernel<<<grid, block>>>(left, right, flow, out);
}

// round 10
// speedup vs baseline: 1.0567x; 1.0360x over previous
#include <cuda_runtime.h>

// Fixed problem shape
#define BB   4
#define CC   256
#define HH   128
#define WW   256
#define NGRP 4
#define CG   64      // channels per group == channels per smem chunk
#define WIN  9       // 1x9 window
#define CK   64      // chunk == one full group
#define SRS  264     // padded smem row: pixel w at col w+4, replicate pad 4 each side

__global__ __launch_bounds__(256, 3)
void crestereo_ck64_kernel(const float* __restrict__ left,
                           const float* __restrict__ right,
                           const float* __restrict__ flow,
                           float* __restrict__ out)
{
    extern __shared__ float srw_raw[];                 // [CK][SRS]
    float (*srw)[SRS] = (float (*)[SRS])srw_raw;

    const int bh = blockIdx.x;
    const int b  = bh >> 7;          // bh / HH
    const int h  = bh & (HH - 1);
    const int w  = threadIdx.x;
    const int HW = HH * WW;

    // ---- per-pixel bilinear setup (identical math to R1) ----
    const float fx = flow[(((size_t)b * 2 + 0) * HH + h) * WW + w];
    const float fy = flow[(((size_t)b * 2 + 1) * HH + h) * WW + w];
    const float x = (float)w + fx;
    const float y = (float)h + fy;
    const float x0f = floorf(x);
    const float y0f = floorf(y);
    const int ix0 = (int)x0f;
    const int iy0 = (int)y0f;
    const float ax = x - x0f;
    const float ay = y - y0f;

    float w00 = (1.f - ax) * (1.f - ay);
    float w01 = ax * (1.f - ay);
    float w10 = (1.f - ax) * ay;
    float w11 = ax * ay;

    const bool vx0 = (ix0     >= 0) & (ix0     <= WW - 1);
    const bool vx1 = (ix0 + 1 >= 0) & (ix0 + 1 <= WW - 1);
    const bool vy0 = (iy0     >= 0) & (iy0     <= HH - 1);
    const bool vy1 = (iy0 + 1 >= 0) & (iy0 + 1 <= HH - 1);
    if (!(vx0 & vy0)) w00 = 0.f;
    if (!(vx1 & vy0)) w01 = 0.f;
    if (!(vx0 & vy1)) w10 = 0.f;
    if (!(vx1 & vy1)) w11 = 0.f;

    const int x0c = min(max(ix0, 0), WW - 1);
    const int x1c = min(max(ix0 + 1, 0), WW - 1);
    const int y0c = min(max(iy0, 0), HH - 1);
    const int y1c = min(max(iy0 + 1, 0), HH - 1);

    const int o00 = y0c * WW + x0c;
    const int o01 = y0c * WW + x1c;
    const int o10 = y1c * WW + x0c;
    const int o11 = y1c * WW + x1c;

    const float* lbase = left  + (size_t)b * CC * HW + (size_t)h * WW + w;
    const float* rbase = right + (size_t)b * CC * HW;

    float acc[WIN];
    const float scale = 1.f / (float)CG;

    for (int g = 0; g < NGRP; ++g) {
        const int ch0 = g * CG;

        __syncthreads();   // protect previous group's readers

        // ---- phase 1: burst-gather 64 channels (one group), full unroll ----
#pragma unroll
        for (int cc = 0; cc < CK; ++cc) {
            const float* rb = rbase + (size_t)(ch0 + cc) * HW;
            float v = rb[o00] * w00;
            v = fmaf(rb[o01], w01, v);
            v = fmaf(rb[o10], w10, v);
            v = fmaf(rb[o11], w11, v);
            srw[cc][4 + w] = v;
            if (w == 0) {
                srw[cc][0] = v; srw[cc][1] = v; srw[cc][2] = v; srw[cc][3] = v;
            }
            if (w == WW - 1) {
                srw[cc][WW + 4] = v; srw[cc][WW + 5] = v;
                srw[cc][WW + 6] = v; srw[cc][WW + 7] = v;
            }
        }
        __syncthreads();

        // ---- phase 2: 9-tap sliding-window accumulate (taps at sp[0..8]) ----
#pragma unroll
        for (int k = 0; k < WIN; ++k) acc[k] = 0.f;

#pragma unroll
        for (int cc = 0; cc < CK; ++cc) {
            const float lv = lbase[(size_t)(ch0 + cc) * HW];
            const float* sp = &srw[cc][w];
#pragma unroll
            for (int k = 0; k < WIN; ++k)
                acc[k] = fmaf(lv, sp[k], acc[k]);
        }

        // ---- write 9 output taps for this group (coalesced across w) ----
        float* ob = out + (((size_t)(b * NGRP + g) * WIN) * HH + h) * WW + w;
#pragma unroll
        for (int k = 0; k < WIN; ++k)
            ob[(size_t)k * HW] = acc[k] * scale;
    }
}

extern "C" void kernel_launch(void* const* d_in, const int* in_sizes, int n_in,
                              void* d_out, int out_size)
{
    const float* left  = (const float*)d_in[0];
    const float* right = (const float*)d_in[1];
    const float* flow  = (const float*)d_in[2];
    float* out = (float*)d_out;

    const int smem_bytes = CK * SRS * (int)sizeof(float);   // 67,584 B
    cudaFuncSetAttribute(crestereo_ck64_kernel,
                         cudaFuncAttributeMaxDynamicSharedMemorySize, smem_bytes);

    dim3 grid(BB * HH);   // 512 blocks: one per (b, h) row
    dim3 block(WW);       // 256 threads
    crestereo_ck64_kernel<<<grid, block, smem_bytes>>>(left, right, flow, out);
}

// round 11
// speedup vs baseline: 2.2070x; 2.0885x over previous
#include <cuda_runtime.h>

// Fixed problem shape
#define BB   4
#define CC   256
#define HH   128
#define WW   256
#define NGRP 4
#define CG   64      // channels per group
#define WIN  9       // window taps (1 x 9)
#define CK   16      // channel chunk held in smem (16 KB -> big L1D carveout)

__global__ __launch_bounds__(256, 3)
void crestereo_corr_kernel(const float* __restrict__ left,
                           const float* __restrict__ right,
                           const float* __restrict__ flow,
                           float* __restrict__ out)
{
    __shared__ float srw[CK][WW];   // warped right row for current channel chunk

    const int bh = blockIdx.x;
    const int b  = bh / HH;
    const int h  = bh % HH;
    const int w  = threadIdx.x;
    const int HW = HH * WW;

    // ---- per-pixel bilinear setup (invariant across channels) ----
    const float fx = flow[(((size_t)b * 2 + 0) * HH + h) * WW + w];
    const float fy = flow[(((size_t)b * 2 + 1) * HH + h) * WW + w];
    const float x = (float)w + fx;
    const float y = (float)h + fy;
    const float x0f = floorf(x);
    const float y0f = floorf(y);
    const int ix0 = (int)x0f;
    const int iy0 = (int)y0f;
    const float ax = x - x0f;
    const float ay = y - y0f;

    float w00 = (1.f - ax) * (1.f - ay);
    float w01 = ax * (1.f - ay);
    float w10 = (1.f - ax) * ay;
    float w11 = ax * ay;

    // zero-padding validity + clamped gather offsets
    const int x0c = min(max(ix0, 0), WW - 1);
    const int x1c = min(max(ix0 + 1, 0), WW - 1);
    const int y0c = min(max(iy0, 0), HH - 1);
    const int y1c = min(max(iy0 + 1, 0), HH - 1);
    if (!(ix0     >= 0 && ix0     <= WW - 1 && iy0     >= 0 && iy0     <= HH - 1)) w00 = 0.f;
    if (!(ix0 + 1 >= 0 && ix0 + 1 <= WW - 1 && iy0     >= 0 && iy0     <= HH - 1)) w01 = 0.f;
    if (!(ix0     >= 0 && ix0     <= WW - 1 && iy0 + 1 >= 0 && iy0 + 1 <= HH - 1)) w10 = 0.f;
    if (!(ix0 + 1 >= 0 && ix0 + 1 <= WW - 1 && iy0 + 1 >= 0 && iy0 + 1 <= HH - 1)) w11 = 0.f;

    const int o00 = y0c * WW + x0c;
    const int o01 = y0c * WW + x1c;
    const int o10 = y1c * WW + x0c;
    const int o11 = y1c * WW + x1c;

    // 9 replicate-clamped sliding-window indices (applied to the WARPED row)
    int widx[WIN];
#pragma unroll
    for (int k = 0; k < WIN; ++k)
        widx[k] = min(max(w + k - 4, 0), WW - 1);

    const float* lbase = left  + (size_t)b * CC * HW + (size_t)h * WW + w;
    const float* rbase = right + (size_t)b * CC * HW;

    float acc[WIN];

    for (int g = 0; g < NGRP; ++g) {
#pragma unroll
        for (int k = 0; k < WIN; ++k) acc[k] = 0.f;

        for (int ch0 = g * CG; ch0 < (g + 1) * CG; ch0 += CK) {
            __syncthreads();   // protect previous chunk's readers

            // phase 1: bilinear warp CK channels of this row into smem
#pragma unroll
            for (int cc = 0; cc < CK; ++cc) {
                const float* rb = rbase + (size_t)(ch0 + cc) * HW;
                float v = rb[o00] * w00 + rb[o01] * w01
                        + rb[o10] * w10 + rb[o11] * w11;
                srw[cc][w] = v;
            }
            __syncthreads();

            // phase 2: sliding-window correlation accumulate
#pragma unroll
            for (int cc = 0; cc < CK; ++cc) {
                const float lv = lbase[(size_t)(ch0 + cc) * HW];
#pragma unroll
                for (int k = 0; k < WIN; ++k)
                    acc[k] += lv * srw[cc][widx[k]];
            }
        }

        // write 9 output taps for this group (coalesced across w)
        const float scale = 1.f / (float)CG;
#pragma unroll
        for (int k = 0; k < WIN; ++k)
            out[((((size_t)b * (NGRP * WIN)) + g * WIN + k) * HH + h) * WW + w]
                = acc[k] * scale;
    }
}

extern "C" void kernel_launch(void* const* d_in, const int* in_sizes, int n_in,
                              void* d_out, int out_size)
{
    const float* left  = (const float*)d_in[0];
    const float* right = (const float*)d_in[1];
    const float* flow  = (const float*)d_in[2];
    float* out = (float*)d_out;

    dim3 grid(BB * HH);   // 512 blocks, one per (b, h) row
    dim3 block(WW);       // 256 threads, one per w
    crestereo_corr_kernel<<<grid, block>>>(left, right, flow, out);
}